// round 4
// baseline (speedup 1.0000x reference)
#include <cuda_runtime.h>
#include <stdint.h>

#define NN 1024
#define EE 32

// Scratch (no allocations allowed)
__device__ float g_part[128];
__device__ unsigned int g_done = 0;

// ---------------------------------------------------------------------------
// Single fused kernel. grid (32 i-tiles, 4 batches) x 256 threads.
// Each CTA: rows [i0,i0+32) x all 1024 j. smem: yT e-major 128KB + norms 4KB.
// Branchless epilogue: T=sum_all e^sim; pos sums via mask-as-float FMAs;
// negatives recovered per row as S = T - A - (1-m_diag)*e^{sigmoid(5)}.
// ---------------------------------------------------------------------------
__global__ void __launch_bounds__(256, 1)
fused_kernel(const float* __restrict__ emb,
             const float* __restrict__ coords,
             const int*   __restrict__ mask,
             float*       __restrict__ out) {
    extern __shared__ char smem[];
    float* sYT  = reinterpret_cast<float*>(smem);   // [32][1024]
    float* sN   = sYT + EE * NN;                    // [1024]
    float* sRed = sN + NN;                          // [8]
    __shared__ int sIsLast;

    const int tid  = threadIdx.x;
    const int b    = blockIdx.y;
    const int i0   = blockIdx.x * 32;
    const int warp = tid >> 5;
    const int lane = tid & 31;

    // ---------------- Phase A: inline prep (4 rows per thread) --------------
#pragma unroll
    for (int k = 0; k < 4; k++) {
        const int j = tid + k * 256;
        const float* ep = emb + ((size_t)(b * NN + j)) * EE;
        float v[EE];
#pragma unroll
        for (int e = 0; e < EE; e += 4) {
            float4 t = *reinterpret_cast<const float4*>(ep + e);
            v[e] = t.x; v[e + 1] = t.y; v[e + 2] = t.z; v[e + 3] = t.w;
        }
        float2 c2 = *reinterpret_cast<const float2*>(coords + ((size_t)(b * NN + j)) * 2);
        v[0] += c2.x;
        v[1] += c2.y;
        float n = 0.f;
#pragma unroll
        for (int e = 0; e < EE; e++) {
            sYT[e * NN + j] = v[e];        // lanes j-consecutive: conflict-free
            n += v[e] * v[e];
        }
        sN[j] = n;
    }
    __syncthreads();

    // ---------------- Phase B: Gram tile + branchless epilogue --------------
    const float4* sYT4 = reinterpret_cast<const float4*>(sYT);
    const float4* sN4  = reinterpret_cast<const float4*>(sN);
    // per-thread mask row pointers, hoisted (alu relief)
    const int* mrow[4];
#pragma unroll
    for (int r = 0; r < 4; r++)
        mrow[r] = mask + ((size_t)b * NN + (size_t)(i0 + warp * 4 + r)) * NN;

    // Per-row: T=sum_all e, A=sum_pos e, Bq=sum_pos e^2, P=sum_pos sim, C=count
    float Tr[4] = {0, 0, 0, 0}, Ar[4] = {0, 0, 0, 0}, Bq[4] = {0, 0, 0, 0};
    float Pr[4] = {0, 0, 0, 0}, Cr[4] = {0, 0, 0, 0};

    float nis[4];
#pragma unroll
    for (int r = 0; r < 4; r++) nis[r] = sN[i0 + warp * 4 + r];

    for (int jc = 0; jc < 8; ++jc) {
        float acc[4][4];
#pragma unroll
        for (int r = 0; r < 4; r++)
#pragma unroll
            for (int c = 0; c < 4; c++) acc[r][c] = 0.f;

#pragma unroll
        for (int e = 0; e < EE; e++) {
            const float4* row = sYT4 + e * (NN / 4);
            float4 a  = row[(i0 >> 2) + warp];     // broadcast across lanes
            float4 bb = row[jc * 32 + lane];       // lane-consecutive
            acc[0][0] += a.x * bb.x; acc[0][1] += a.x * bb.y; acc[0][2] += a.x * bb.z; acc[0][3] += a.x * bb.w;
            acc[1][0] += a.y * bb.x; acc[1][1] += a.y * bb.y; acc[1][2] += a.y * bb.z; acc[1][3] += a.y * bb.w;
            acc[2][0] += a.z * bb.x; acc[2][1] += a.z * bb.y; acc[2][2] += a.z * bb.z; acc[2][3] += a.z * bb.w;
            acc[3][0] += a.w * bb.x; acc[3][1] += a.w * bb.y; acc[3][2] += a.w * bb.z; acc[3][3] += a.w * bb.w;
        }

        const int jb = jc * 128 + lane * 4;
        float4 njv = sN4[jb >> 2];
        float nj[4] = {njv.x, njv.y, njv.z, njv.w};

#pragma unroll
        for (int r = 0; r < 4; r++) {
            const float ni = nis[r];
            int4 m4 = *reinterpret_cast<const int4*>(mrow[r] + jb);
            float mf[4] = {(float)m4.x, (float)m4.y, (float)m4.z, (float)m4.w};
#pragma unroll
            for (int c = 0; c < 4; c++) {
                float ssq  = fmaxf(fmaf(-2.f, acc[r][c], ni + nj[c]), 0.f);
                float dist = sqrtf(ssq);                    // MUFU.SQRT, sqrt(0)=0
                float u    = __expf(dist - 5.f);
                float sim  = __fdividef(1.f, 1.f + u);      // sigmoid(5-dist)
                float ex   = __expf(sim);
                float m    = mf[c];
                Tr[r] += ex;
                Ar[r]  = fmaf(m, ex, Ar[r]);
                Bq[r]  = fmaf(m, ex * ex, Bq[r]);
                Pr[r]  = fmaf(m, sim, Pr[r]);
                Cr[r] += m;
            }
        }
    }

    // diag mask values for this warp's 4 rows (lanes 0..3 load)
    int mdiag_l = 0;
    if (lane < 4) {
        const int i = i0 + warp * 4 + lane;
        mdiag_l = mask[((size_t)b * NN + i) * NN + i];
    }

    // ---------------- Phase C: row closed form + reductions -----------------
    const float EXDIAG = 2.70009072f;   // e^{sigmoid(5)}
    float csum = 0.f;
#pragma unroll
    for (int r = 0; r < 4; r++) {
        float t = Tr[r], a = Ar[r], bq = Bq[r], p = Pr[r], cn = Cr[r];
#pragma unroll
        for (int o = 16; o > 0; o >>= 1) {
            t  += __shfl_down_sync(0xffffffffu, t,  o);
            a  += __shfl_down_sync(0xffffffffu, a,  o);
            bq += __shfl_down_sync(0xffffffffu, bq, o);
            p  += __shfl_down_sync(0xffffffffu, p,  o);
            cn += __shfl_down_sync(0xffffffffu, cn, o);
        }
        float md = (float)__shfl_sync(0xffffffffu, mdiag_l, r);
        if (lane == 0) {
            float S  = t - a - (1.f - md) * EXDIAG;   // negatives' exp-sum
            float L  = __logf(S);
            float rS = __fdividef(1.f, S);
            // sum_pos [L - sim + log1p(e^sim / S)], log1p to 2nd order
            csum += cn * L - p + a * rS - 0.5f * bq * rS * rS;
        }
    }
    if (lane == 0) sRed[warp] = csum;
    __syncthreads();

    if (tid == 0) {
        float tsum = 0.f;
#pragma unroll
        for (int w = 0; w < 8; w++) tsum += sRed[w];
        g_part[b * 32 + blockIdx.x] = tsum;
        __threadfence();
        unsigned v = atomicAdd(&g_done, 1u);
        sIsLast = (v == 127u);
    }
    __syncthreads();

    // Last CTA: deterministic fixed-order tree over the 128 partials
    if (sIsLast) {
        double* dsh = reinterpret_cast<double*>(sYT);   // reuse smem
        if (tid < 128) dsh[tid] = (double)g_part[tid];
        __syncthreads();
#pragma unroll
        for (int s = 64; s > 0; s >>= 1) {
            if (tid < s) dsh[tid] += dsh[tid + s];
            __syncthreads();
        }
        if (tid == 0) {
            out[0] = (float)dsh[0];
            g_done = 0;                 // reset for next replay
        }
    }
}

// ---------------------------------------------------------------------------
extern "C" void kernel_launch(void* const* d_in, const int* in_sizes, int n_in,
                              void* d_out, int out_size) {
    (void)in_sizes; (void)n_in; (void)out_size;
    const float* emb    = (const float*)d_in[0];   // [4,1024,32]
    const float* coords = (const float*)d_in[1];   // [4,1024,2]
    const int*   mask   = (const int*)d_in[2];     // [4,1024,1024] bool->int32
    float* out          = (float*)d_out;           // scalar

    size_t smem = (size_t)EE * NN * sizeof(float)   // yT    131072
                + (size_t)NN * sizeof(float)        // norms   4096
                + 64;                               // reduction slots
    cudaFuncSetAttribute(fused_kernel, cudaFuncAttributeMaxDynamicSharedMemorySize,
                         (int)smem);
    fused_kernel<<<dim3(32, 4), 256, smem>>>(emb, coords, mask, out);
}